// round 6
// baseline (speedup 1.0000x reference)
#include <cuda_runtime.h>
#include <cuda_bf16.h>
#include <cstdint>

// Problem dims: B=8, T=2048 -> N=16384 tokens, D=512, E=8, H=1024, top_k=2
#define N_TOK   16384
#define D_DIM   512
#define E_EXP   8
#define H_DIM   1024
#define NPAIR   (2 * N_TOK)
#define RBLK    (N_TOK / 8)

#define BM 128
#define BN 128
#define KCH 128                      // 128 int8 = 128B of data per row per chunk
#define ROWB 144                     // smem row stride (128B data + 16B pad)
#define TILE_BYTES (128 * ROWB)      // 18432
#define STAGE_BYTES (4 * TILE_BYTES) // Aqh, Aql, Bqh, Bql = 73728
#define NSTAGE 3
#define SMEM_DYN (1024 + NSTAGE * STAGE_BYTES)   // 222208 B

#define QMAX 32000.0f

// ---------------- scratch (static device globals) ----------------
__device__ __align__(1024) char  g_xqh[(size_t)N_TOK * D_DIM];
__device__ __align__(1024) char  g_xql[(size_t)N_TOK * D_DIM];
__device__ float g_sx[N_TOK];
__device__ __align__(1024) char  g_w1qh[(size_t)E_EXP * H_DIM * D_DIM];  // [E][H][D] K-major
__device__ __align__(1024) char  g_w1ql[(size_t)E_EXP * H_DIM * D_DIM];
__device__ float g_t1[E_EXP * H_DIM];
__device__ __align__(1024) char  g_w2qh[(size_t)E_EXP * D_DIM * H_DIM];  // [E][D][H] K-major
__device__ __align__(1024) char  g_w2ql[(size_t)E_EXP * D_DIM * H_DIM];
__device__ float g_t2[E_EXP * D_DIM];
__device__ __align__(1024) float g_h[(size_t)NPAIR * H_DIM];             // fp32 hidden
__device__ __align__(1024) char  g_hqh[(size_t)NPAIR * H_DIM];
__device__ __align__(1024) char  g_hql[(size_t)NPAIR * H_DIM];
__device__ float g_sh[NPAIR];
__device__ __align__(1024) float g_out2[(size_t)NPAIR * D_DIM];
__device__ int   g_tok[NPAIR];
__device__ float g_w[NPAIR];
__device__ int   g_slot[NPAIR];
__device__ int   g_topi[NPAIR];
__device__ float g_topw[NPAIR];
__device__ int   g_cnt[E_EXP];
__device__ int   g_cnt2[E_EXP];
__device__ int   g_off[E_EXP];
__device__ float g_psums[RBLK * E_EXP];

// ---------------- PTX helpers (baseline ISA only) ----------------
__device__ __forceinline__ uint32_t smem_u32(const void* p) {
    uint32_t a;
    asm("{ .reg .u64 t; cvta.to.shared.u64 t, %1; cvt.u32.u64 %0, t; }" : "=r"(a) : "l"(p));
    return a;
}
__device__ __forceinline__ void cp16(uint32_t dst, const void* src) {
    asm volatile("cp.async.cg.shared.global [%0], [%1], 16;" :: "r"(dst), "l"(src));
}
__device__ __forceinline__ uint32_t lds32(uint32_t addr) {
    uint32_t v;
    asm volatile("ld.shared.b32 %0, [%1];" : "=r"(v) : "r"(addr));
    return v;
}
// s8 MMA, s32 accumulate: D[16x8] += A[16x32] * B[32x8]
__device__ __forceinline__ void mma_s8(int* c, const uint32_t* a, uint32_t b0, uint32_t b1) {
    asm volatile(
        "mma.sync.aligned.m16n8k32.row.col.s32.s8.s8.s32 "
        "{%0,%1,%2,%3}, {%4,%5,%6,%7}, {%8,%9}, {%0,%1,%2,%3};"
        : "+r"(c[0]), "+r"(c[1]), "+r"(c[2]), "+r"(c[3])
        : "r"(a[0]), "r"(a[1]), "r"(a[2]), "r"(a[3]), "r"(b0), "r"(b1));
}
// split q (|q|<=32512) into q = 256*qh + ql with qh,ql in [-128,127]
__device__ __forceinline__ void qsplit(float v, float inv, int& qh, int& ql) {
    int q = __float2int_rn(v * inv);
    qh = (q + 128) >> 8;
    ql = q - (qh << 8);
}
__device__ __forceinline__ uint32_t pack4(int a, int b, int c, int d) {
    return (uint32_t)(uint8_t)a | ((uint32_t)(uint8_t)b << 8) |
           ((uint32_t)(uint8_t)c << 16) | ((uint32_t)(uint8_t)d << 24);
}

// ---------------- init ----------------
__global__ void init_kernel() {
    int t = threadIdx.x;
    if (t < E_EXP) { g_cnt[t] = 0; g_cnt2[t] = 0; }
}

// ---------------- router ----------------
__global__ void router_kernel(const float* __restrict__ x,
                              const float* __restrict__ Wr,
                              const float* __restrict__ br) {
    __shared__ float ps[8][E_EXP];
    const int wid = threadIdx.x >> 5, lane = threadIdx.x & 31;
    const int n = blockIdx.x * 8 + wid;
    const float* xr = x + (size_t)n * D_DIM;
    float acc[E_EXP];
#pragma unroll
    for (int e = 0; e < E_EXP; e++) acc[e] = 0.f;
    for (int i = lane; i < D_DIM; i += 32) {
        float xv = xr[i];
        const float* w = Wr + i * E_EXP;
#pragma unroll
        for (int e = 0; e < E_EXP; e++) acc[e] += xv * w[e];
    }
#pragma unroll
    for (int e = 0; e < E_EXP; e++)
#pragma unroll
        for (int o = 16; o > 0; o >>= 1)
            acc[e] += __shfl_xor_sync(0xffffffffu, acc[e], o);

    if (lane == 0) {
        float mx = -1e30f;
#pragma unroll
        for (int e = 0; e < E_EXP; e++) { acc[e] += br[e]; mx = fmaxf(mx, acc[e]); }
        float s = 0.f;
#pragma unroll
        for (int e = 0; e < E_EXP; e++) { acc[e] = expf(acc[e] - mx); s += acc[e]; }
        const float inv = 1.f / s;
        float p1 = -1.f, p2 = -1.f; int i1 = 0, i2 = 0;
#pragma unroll
        for (int e = 0; e < E_EXP; e++) {
            float p = acc[e] * inv;
            ps[wid][e] = p;
            if (p > p1)      { p2 = p1; i2 = i1; p1 = p; i1 = e; }
            else if (p > p2) { p2 = p; i2 = e; }
        }
        g_topi[2 * n] = i1;     g_topw[2 * n] = p1;
        g_topi[2 * n + 1] = i2; g_topw[2 * n + 1] = p2;
        atomicAdd(&g_cnt[i1], 1);
        atomicAdd(&g_cnt[i2], 1);
    }
    __syncthreads();
    if (threadIdx.x < E_EXP) {
        float s = 0.f;
#pragma unroll
        for (int w = 0; w < 8; w++) s += ps[w][threadIdx.x];
        g_psums[blockIdx.x * E_EXP + threadIdx.x] = s;
    }
}

// ---------------- offsets + gating loss ----------------
__global__ void offsets_loss_kernel(float* __restrict__ out, int out_size) {
    __shared__ float dsq[E_EXP];
    const int tid = threadIdx.x;
    if (tid == 0) {
        int o = 0;
        for (int e = 0; e < E_EXP; e++) { g_off[e] = o; o += g_cnt[e]; }
    }
    const int wid = tid >> 5, lane = tid & 31;
    if (wid < E_EXP) {
        float s = 0.f;
        for (int b = lane; b < RBLK; b += 32) s += g_psums[b * E_EXP + wid];
#pragma unroll
        for (int o = 16; o > 0; o >>= 1) s += __shfl_xor_sync(0xffffffffu, s, o);
        if (lane == 0) {
            float mean = s / (float)N_TOK;
            float d = (1.0f / E_EXP) - mean;
            dsq[wid] = d * d;
        }
    }
    __syncthreads();
    if (tid == 0 && out_size > N_TOK * D_DIM) {
        float l = 0.f;
        for (int e = 0; e < E_EXP; e++) l += dsq[e];
        out[N_TOK * D_DIM] = (l / E_EXP) * 1e-4f;
    }
}

// ---------------- scatter ----------------
__global__ void scatter_kernel() {
    const int n = blockIdx.x * blockDim.x + threadIdx.x;
    if (n >= N_TOK) return;
#pragma unroll
    for (int k = 0; k < 2; k++) {
        int e = g_topi[2 * n + k];
        int i = atomicAdd(&g_cnt2[e], 1);
        int p = g_off[e] + i;
        g_tok[p] = n;
        g_w[p] = g_topw[2 * n + k];
        g_slot[2 * n + k] = p;
    }
}

// ---------------- x -> int8 dual-plane (per-token scale) ----------------
__global__ void quant_x_kernel(const float* __restrict__ x) {
    const int wid = threadIdx.x >> 5, lane = threadIdx.x & 31;
    const int n = blockIdx.x * 8 + wid;
    const float4* xr = (const float4*)(x + (size_t)n * D_DIM);
    float4 v[4];
    float mx = 0.f;
#pragma unroll
    for (int i = 0; i < 4; i++) {
        v[i] = xr[lane * 4 + i];
        mx = fmaxf(mx, fmaxf(fmaxf(fabsf(v[i].x), fabsf(v[i].y)),
                             fmaxf(fabsf(v[i].z), fabsf(v[i].w))));
    }
#pragma unroll
    for (int o = 16; o > 0; o >>= 1) mx = fmaxf(mx, __shfl_xor_sync(0xffffffffu, mx, o));
    mx = fmaxf(mx, 1e-20f);
    const float inv = QMAX / mx;
    if (lane == 0) g_sx[n] = mx / QMAX;
    uint32_t ph[4], pl[4];
#pragma unroll
    for (int i = 0; i < 4; i++) {
        int h0, l0, h1, l1, h2, l2, h3, l3;
        qsplit(v[i].x, inv, h0, l0); qsplit(v[i].y, inv, h1, l1);
        qsplit(v[i].z, inv, h2, l2); qsplit(v[i].w, inv, h3, l3);
        ph[i] = pack4(h0, h1, h2, h3);
        pl[i] = pack4(l0, l1, l2, l3);
    }
    ((uint4*)(g_xqh + (size_t)n * D_DIM))[lane] = make_uint4(ph[0], ph[1], ph[2], ph[3]);
    ((uint4*)(g_xql + (size_t)n * D_DIM))[lane] = make_uint4(pl[0], pl[1], pl[2], pl[3]);
}

// ---------------- weight column max (over K) ----------------
template <int K, int N>
__global__ void wmax_kernel(const float* __restrict__ W, float* __restrict__ T) {
    const int e = blockIdx.y;
    const int n = blockIdx.x * 256 + threadIdx.x;
    const float* base = W + (size_t)e * K * N + n;
    float m = 0.f;
    for (int k = 0; k < K; k++) m = fmaxf(m, fabsf(base[(size_t)k * N]));
    T[e * N + n] = fmaxf(m, 1e-20f) / QMAX;
}

// ---------------- weight transpose + int8 quantize: [E][K][N] -> [E][N][K] ----------------
template <int K, int N>
__global__ void transpose_quant_kernel(const float* __restrict__ W,
                                       const float* __restrict__ T,
                                       char* __restrict__ Qh, char* __restrict__ Ql) {
    __shared__ float t[32][33];
    const int e = blockIdx.z;
    const int n0 = blockIdx.x * 32, k0 = blockIdx.y * 32;
    const int tx = threadIdx.x, ty = threadIdx.y;
    for (int i = ty; i < 32; i += 8)
        t[i][tx] = W[((size_t)e * K + k0 + i) * N + n0 + tx];
    __syncthreads();
    for (int i = ty; i < 32; i += 8) {
        float inv = 1.f / T[e * N + n0 + i];    // = QMAX / colmax
        float v = t[tx][i];                     // = W[e][k0+tx][n0+i]
        int qh, ql;
        qsplit(v, inv, qh, ql);
        size_t o = ((size_t)e * N + n0 + i) * K + k0 + tx;
        Qh[o] = (char)qh;
        Ql[o] = (char)ql;
    }
}

// ---------------- h (fp32) -> int8 dual-plane (per-pair-row scale) ----------------
__global__ void quant_h_kernel() {
    __shared__ float red[8];
    const int row = blockIdx.x;
    const int tid = threadIdx.x;
    const int wid = tid >> 5, lane = tid & 31;
    float4 v = ((const float4*)(g_h + (size_t)row * H_DIM))[tid];
    float mx = fmaxf(fmaxf(fabsf(v.x), fabsf(v.y)), fmaxf(fabsf(v.z), fabsf(v.w)));
#pragma unroll
    for (int o = 16; o > 0; o >>= 1) mx = fmaxf(mx, __shfl_xor_sync(0xffffffffu, mx, o));
    if (lane == 0) red[wid] = mx;
    __syncthreads();
    float m = 1e-20f;
#pragma unroll
    for (int i = 0; i < 8; i++) m = fmaxf(m, red[i]);
    const float inv = QMAX / m;
    if (tid == 0) g_sh[row] = m / QMAX;
    int h0, l0, h1, l1, h2, l2, h3, l3;
    qsplit(v.x, inv, h0, l0); qsplit(v.y, inv, h1, l1);
    qsplit(v.z, inv, h2, l2); qsplit(v.w, inv, h3, l3);
    ((uint32_t*)g_hqh)[(size_t)row * 256 + tid] = pack4(h0, h1, h2, h3);
    ((uint32_t*)g_hql)[(size_t)row * 256 + tid] = pack4(l0, l1, l2, l3);
}

// ---------------- int8 dual-plane GEMM via mma.m16n8k32.s8 ----------------
// PASS2=false: h = leaky(gather(xq) @ W1q^T + b1) -> g_h (fp32),  KDIM=512,  NCOL=1024
// PASS2=true : o = w * leaky(hq @ W2q^T + b2)     -> g_out2,      KDIM=1024, NCOL=512
template <bool PASS2, int KDIM, int NCOL>
__global__ void __launch_bounds__(256, 1)
gemm_s8(const float* __restrict__ bias) {
    extern __shared__ char smem[];
    const int e = blockIdx.z;
    const int cnt = g_cnt[e];
    const int m0 = blockIdx.y * BM;
    if (m0 >= cnt) return;
    const int n0 = blockIdx.x * BN;
    const int off = g_off[e];
    const int tid = threadIdx.x;
    const int wid = tid >> 5, lane = tid & 31;
    const int warp_m = wid >> 2;                 // 0..1 (64 rows)
    const int warp_n = wid & 3;                  // 0..3 (32 cols)
    const int qr = lane >> 2;                    // 0..7
    const int qc4 = (lane & 3) * 4;              // byte offset within k-group
    const int qc2 = (lane & 3) * 2;              // C-frag column pair

    const uint32_t sbase = smem_u32(smem);
    int* toks = (int*)smem;                      // [0,512)
    const uint32_t TILE0 = 1024;

    if (!PASS2) {
        if (tid < BM) {
            int m = m0 + tid;
            toks[tid] = g_tok[off + (m < cnt ? m : cnt - 1)];
        }
        __syncthreads();
    }

    const char* Ahb = PASS2 ? g_hqh : g_xqh;
    const char* Alb = PASS2 ? g_hql : g_xql;
    const char* Bhb = PASS2 ? g_w2qh : g_w1qh;
    const char* Blb = PASS2 ? g_w2ql : g_w1ql;
    const float* Tb = (PASS2 ? g_t2 : g_t1) + e * NCOL + n0;

    // cp.async plan: 4 units of 16B per tile type (128 rows x 8 units)
    size_t aoff[4], boff[4];
    uint32_t dst[4];
#pragma unroll
    for (int t = 0; t < 4; t++) {
        int uu = tid + 256 * t;
        int r = uu >> 3, u = uu & 7;
        dst[t] = (uint32_t)(r * ROWB + u * 16);
        if (!PASS2) {
            aoff[t] = (size_t)toks[r] * KDIM + u * 16;
        } else {
            int m = m0 + r;
            int row = off + (m < cnt ? m : cnt - 1);
            aoff[t] = (size_t)row * KDIM + u * 16;
        }
        boff[t] = (size_t)(e * NCOL + n0 + r) * KDIM + u * 16;
    }

    auto issue_loads = [&](int c, int s) {
        const uint32_t st = sbase + TILE0 + s * STAGE_BYTES;
        const size_t kb = (size_t)c * KCH;
#pragma unroll
        for (int t = 0; t < 4; t++) {
            cp16(st + dst[t],                  Ahb + aoff[t] + kb);
            cp16(st + TILE_BYTES + dst[t],     Alb + aoff[t] + kb);
            cp16(st + 2 * TILE_BYTES + dst[t], Bhb + boff[t] + kb);
            cp16(st + 3 * TILE_BYTES + dst[t], Blb + boff[t] + kb);
        }
        asm volatile("cp.async.commit_group;" ::: "memory");
    };

    int accH[4][4][4], accM[4][4][4];
#pragma unroll
    for (int f = 0; f < 4; f++)
#pragma unroll
        for (int g = 0; g < 4; g++)
#pragma unroll
            for (int q = 0; q < 4; q++) { accH[f][g][q] = 0; accM[f][g][q] = 0; }

    constexpr int C = KDIM / KCH;
    issue_loads(0, 0);
    issue_loads(1, 1);

    uint32_t aRow[4], bRow[4];
#pragma unroll
    for (int f = 0; f < 4; f++) aRow[f] = (uint32_t)((warp_m * 64 + f * 16 + qr) * ROWB);
#pragma unroll
    for (int g = 0; g < 4; g++) bRow[g] = (uint32_t)((warp_n * 32 + g * 8 + qr) * ROWB);

    for (int c = 0; c < C; c++) {
        const int s = c % NSTAGE;
        if (c == C - 1) asm volatile("cp.async.wait_group 0;" ::: "memory");
        else            asm volatile("cp.async.wait_group 1;" ::: "memory");
        __syncthreads();
        if (c + 2 < C) issue_loads(c + 2, (c + 2) % NSTAGE);

        const uint32_t stAh = sbase + TILE0 + s * STAGE_BYTES;
        const uint32_t stAl = stAh + TILE_BYTES;
        const uint32_t stBh = stAh + 2 * TILE_BYTES;
        const uint32_t stBl = stAh + 3 * TILE_BYTES;

#pragma unroll
        for (int ks = 0; ks < 4; ks++) {                 // 4 x k32 per 128-K chunk
            const uint32_t kb = (uint32_t)(ks * 32 + qc4);
            uint32_t ah[4][4], al[4][4];
#pragma unroll
            for (int f = 0; f < 4; f++) {
                ah[f][0] = lds32(stAh + aRow[f] + kb);
                ah[f][1] = lds32(stAh + aRow[f] + 8 * ROWB + kb);
                ah[f][2] = lds32(stAh + aRow[f] + kb + 16);
                ah[f][3] = lds32(stAh + aRow[f] + 8 * ROWB + kb + 16);
                al[f][0] = lds32(stAl + aRow[f] + kb);
                al[f][1] = lds32(stAl + aRow[f] + 8 * ROWB + kb);
                al[f][2] = lds32(stAl + aRow[f] + kb + 16);
                al[f][3] = lds32(stAl + aRow[f] + 8 * ROWB + kb + 16);
            }
#pragma unroll
            for (int g = 0; g < 4; g++) {
                uint32_t bh0 = lds32(stBh + bRow[g] + kb);
                uint32_t bh1 = lds32(stBh + bRow[g] + kb + 16);
                uint32_t bl0 = lds32(stBl + bRow[g] + kb);
                uint32_t bl1 = lds32(stBl + bRow[g] + kb + 16);
#pragma unroll
                for (int f = 0; f < 4; f++) {
                    mma_s8(accH[f][g], ah[f], bh0, bh1);   // qh*ph  (x65536)
                    mma_s8(accM[f][g], ah[f], bl0, bl1);   // qh*pl  (x256)
                    mma_s8(accM[f][g], al[f], bh0, bh1);   // ql*ph  (x256)
                }
            }
        }
        __syncthreads();
    }

    // ---- epilogue: reconstruct fp32, bias + leaky (+wgt), direct stores ----
    const float* bb = bias + e * NCOL + n0;
#pragma unroll
    for (int f = 0; f < 4; f++) {
        const int rbase = warp_m * 64 + f * 16 + qr;
#pragma unroll
        for (int half = 0; half < 2; half++) {
            const int row = rbase + half * 8;
            const int m = m0 + row;
            if (m >= cnt) continue;
            const int grow = off + m;
            const float sA = PASS2 ? g_sh[grow] : g_sx[toks[row]];
            float wgt = 0.f;
            if (PASS2) wgt = g_w[grow];
#pragma unroll
            for (int g = 0; g < 4; g++) {
                const int col = warp_n * 32 + g * 8 + qc2;
                const float2 tB = *(const float2*)&Tb[col];
                float v0 = 65536.f * (float)accH[f][g][2 * half + 0]
                         +   256.f * (float)accM[f][g][2 * half + 0];
                float v1 = 65536.f * (float)accH[f][g][2 * half + 1]
                         +   256.f * (float)accM[f][g][2 * half + 1];
                v0 = sA * tB.x * v0 + bb[col];
                v1 = sA * tB.y * v1 + bb[col + 1];
                v0 = (v0 > 0.f) ? v0 : 0.01f * v0;
                v1 = (v1 > 0.f) ? v1 : 0.01f * v1;
                const size_t base = (size_t)grow * NCOL + n0 + col;
                if (!PASS2) {
                    *(float2*)&g_h[base] = make_float2(v0, v1);
                } else {
                    *(float2*)&g_out2[base] = make_float2(wgt * v0, wgt * v1);
                }
            }
        }
    }
}

// ---------------- combine ----------------
__global__ void combine_kernel(float* __restrict__ out) {
    const int t = blockIdx.x * blockDim.x + threadIdx.x;
    if (t >= N_TOK * (D_DIM / 4)) return;
    const int n = t / (D_DIM / 4);
    const int d = (t % (D_DIM / 4)) * 4;
    const int s0 = g_slot[2 * n], s1 = g_slot[2 * n + 1];
    float4 a = *(const float4*)(g_out2 + (size_t)s0 * D_DIM + d);
    float4 b = *(const float4*)(g_out2 + (size_t)s1 * D_DIM + d);
    float4 r; r.x = a.x + b.x; r.y = a.y + b.y; r.z = a.z + b.z; r.w = a.w + b.w;
    *(float4*)(out + (size_t)n * D_DIM + d) = r;
}

extern "C" void kernel_launch(void* const* d_in, const int* in_sizes, int n_in,
                              void* d_out, int out_size) {
    const float* x  = (const float*)d_in[0];
    const float* Wr = (const float*)d_in[1];
    const float* br = (const float*)d_in[2];
    const float* W1 = (const float*)d_in[3];
    const float* b1 = (const float*)d_in[4];
    const float* W2 = (const float*)d_in[5];
    const float* b2 = (const float*)d_in[6];
    float* out = (float*)d_out;

    cudaFuncSetAttribute(gemm_s8<false, D_DIM, H_DIM>,
                         cudaFuncAttributeMaxDynamicSharedMemorySize, SMEM_DYN);
    cudaFuncSetAttribute(gemm_s8<true, H_DIM, D_DIM>,
                         cudaFuncAttributeMaxDynamicSharedMemorySize, SMEM_DYN);

    // REAL device addresses of __device__ scratch (never pass symbols from host!)
    float *t1, *t2;
    char *w1qh, *w1ql, *w2qh, *w2ql;
    cudaGetSymbolAddress((void**)&t1,   g_t1);
    cudaGetSymbolAddress((void**)&t2,   g_t2);
    cudaGetSymbolAddress((void**)&w1qh, g_w1qh);
    cudaGetSymbolAddress((void**)&w1ql, g_w1ql);
    cudaGetSymbolAddress((void**)&w2qh, g_w2qh);
    cudaGetSymbolAddress((void**)&w2ql, g_w2ql);

    init_kernel<<<1, 32>>>();
    router_kernel<<<RBLK, 256>>>(x, Wr, br);
    offsets_loss_kernel<<<1, 256>>>(out, out_size);
    scatter_kernel<<<(N_TOK + 255) / 256, 256>>>();
    quant_x_kernel<<<N_TOK / 8, 256>>>(x);
    wmax_kernel<D_DIM, H_DIM><<<dim3(H_DIM / 256, E_EXP), 256>>>(W1, t1);
    wmax_kernel<H_DIM, D_DIM><<<dim3(D_DIM / 256, E_EXP), 256>>>(W2, t2);
    transpose_quant_kernel<D_DIM, H_DIM>
        <<<dim3(H_DIM / 32, D_DIM / 32, E_EXP), dim3(32, 8)>>>(W1, t1, w1qh, w1ql);
    transpose_quant_kernel<H_DIM, D_DIM>
        <<<dim3(D_DIM / 32, H_DIM / 32, E_EXP), dim3(32, 8)>>>(W2, t2, w2qh, w2ql);

    gemm_s8<false, D_DIM, H_DIM>
        <<<dim3(H_DIM / BN, N_TOK / BM, E_EXP), 256, SMEM_DYN>>>(b1);
    quant_h_kernel<<<NPAIR, 256>>>();
    gemm_s8<true, H_DIM, D_DIM>
        <<<dim3(D_DIM / BN, N_TOK / BM, E_EXP), 256, SMEM_DYN>>>(b2);
    combine_kernel<<<(N_TOK * D_DIM / 4 + 255) / 256, 256>>>(out);
}

// round 7
// speedup vs baseline: 2.8445x; 2.8445x over previous
#include <cuda_runtime.h>
#include <cuda_fp16.h>
#include <cstdint>

// Problem dims: B=8, T=2048 -> N=16384 tokens, D=512, E=8, H=1024, top_k=2
#define N_TOK   16384
#define D_DIM   512
#define E_EXP   8
#define H_DIM   1024
#define NPAIR   (2 * N_TOK)
#define RBLK    (N_TOK / 8)

#define BM 128
#define BN 128
#define KCH 64                       // 64 fp16 = 128B of data per row per chunk
#define ROWB 144                     // smem row stride (128B data + 16B pad)
#define TILE_BYTES (128 * ROWB)      // 18432
#define STAGE_BYTES (3 * TILE_BYTES) // Ah, Al, B = 55296
#define NSTAGE 3
#define SMEM_DYN (1024 + NSTAGE * STAGE_BYTES)   // 166912 B

// ---------------- scratch (static device globals) ----------------
__device__ __align__(1024) __half g_xh[(size_t)N_TOK * D_DIM];
__device__ __align__(1024) __half g_xl[(size_t)N_TOK * D_DIM];
__device__ __align__(1024) __half g_w1q[(size_t)E_EXP * H_DIM * D_DIM]; // [E][H][D] K-major
__device__ __align__(1024) __half g_w2q[(size_t)E_EXP * D_DIM * H_DIM]; // [E][D][H] K-major
__device__ __align__(1024) __half g_hh[(size_t)NPAIR * H_DIM];
__device__ __align__(1024) __half g_hl[(size_t)NPAIR * H_DIM];
__device__ __align__(1024) float g_out2[(size_t)NPAIR * D_DIM];
__device__ int   g_tok[NPAIR];
__device__ float g_w[NPAIR];
__device__ int   g_slot[NPAIR];
__device__ int   g_topi[NPAIR];
__device__ float g_topw[NPAIR];
__device__ int   g_cnt[E_EXP];
__device__ int   g_cnt2[E_EXP];
__device__ int   g_off[E_EXP];
__device__ float g_psums[RBLK * E_EXP];

// ---------------- PTX helpers (baseline ISA only) ----------------
__device__ __forceinline__ uint32_t smem_u32(const void* p) {
    uint32_t a;
    asm("{ .reg .u64 t; cvta.to.shared.u64 t, %1; cvt.u32.u64 %0, t; }" : "=r"(a) : "l"(p));
    return a;
}
__device__ __forceinline__ void cp16(uint32_t dst, const void* src) {
    asm volatile("cp.async.cg.shared.global [%0], [%1], 16;" :: "r"(dst), "l"(src));
}
__device__ __forceinline__ uint32_t lds32(uint32_t addr) {
    uint32_t v;
    asm volatile("ld.shared.b32 %0, [%1];" : "=r"(v) : "r"(addr));
    return v;
}
__device__ __forceinline__ void mma_f16(float* c, const uint32_t* a, uint32_t b0, uint32_t b1) {
    asm volatile(
        "mma.sync.aligned.m16n8k16.row.col.f32.f16.f16.f32 "
        "{%0,%1,%2,%3}, {%4,%5,%6,%7}, {%8,%9}, {%0,%1,%2,%3};"
        : "+f"(c[0]), "+f"(c[1]), "+f"(c[2]), "+f"(c[3])
        : "r"(a[0]), "r"(a[1]), "r"(a[2]), "r"(a[3]), "r"(b0), "r"(b1));
}

// ---------------- init ----------------
__global__ void init_kernel() {
    int t = threadIdx.x;
    if (t < E_EXP) { g_cnt[t] = 0; g_cnt2[t] = 0; }
}

// ---------------- router ----------------
__global__ void router_kernel(const float* __restrict__ x,
                              const float* __restrict__ Wr,
                              const float* __restrict__ br) {
    __shared__ float ps[8][E_EXP];
    const int wid = threadIdx.x >> 5, lane = threadIdx.x & 31;
    const int n = blockIdx.x * 8 + wid;
    const float* xr = x + (size_t)n * D_DIM;
    float acc[E_EXP];
#pragma unroll
    for (int e = 0; e < E_EXP; e++) acc[e] = 0.f;
    for (int i = lane; i < D_DIM; i += 32) {
        float xv = xr[i];
        const float* w = Wr + i * E_EXP;
#pragma unroll
        for (int e = 0; e < E_EXP; e++) acc[e] += xv * w[e];
    }
#pragma unroll
    for (int e = 0; e < E_EXP; e++)
#pragma unroll
        for (int o = 16; o > 0; o >>= 1)
            acc[e] += __shfl_xor_sync(0xffffffffu, acc[e], o);

    if (lane == 0) {
        float mx = -1e30f;
#pragma unroll
        for (int e = 0; e < E_EXP; e++) { acc[e] += br[e]; mx = fmaxf(mx, acc[e]); }
        float s = 0.f;
#pragma unroll
        for (int e = 0; e < E_EXP; e++) { acc[e] = expf(acc[e] - mx); s += acc[e]; }
        const float inv = 1.f / s;
        float p1 = -1.f, p2 = -1.f; int i1 = 0, i2 = 0;
#pragma unroll
        for (int e = 0; e < E_EXP; e++) {
            float p = acc[e] * inv;
            ps[wid][e] = p;
            if (p > p1)      { p2 = p1; i2 = i1; p1 = p; i1 = e; }
            else if (p > p2) { p2 = p; i2 = e; }
        }
        g_topi[2 * n] = i1;     g_topw[2 * n] = p1;
        g_topi[2 * n + 1] = i2; g_topw[2 * n + 1] = p2;
        atomicAdd(&g_cnt[i1], 1);
        atomicAdd(&g_cnt[i2], 1);
    }
    __syncthreads();
    if (threadIdx.x < E_EXP) {
        float s = 0.f;
#pragma unroll
        for (int w = 0; w < 8; w++) s += ps[w][threadIdx.x];
        g_psums[blockIdx.x * E_EXP + threadIdx.x] = s;
    }
}

// ---------------- offsets + gating loss ----------------
__global__ void offsets_loss_kernel(float* __restrict__ out, int out_size) {
    __shared__ float dsq[E_EXP];
    const int tid = threadIdx.x;
    if (tid == 0) {
        int o = 0;
        for (int e = 0; e < E_EXP; e++) { g_off[e] = o; o += g_cnt[e]; }
    }
    const int wid = tid >> 5, lane = tid & 31;
    if (wid < E_EXP) {
        float s = 0.f;
        for (int b = lane; b < RBLK; b += 32) s += g_psums[b * E_EXP + wid];
#pragma unroll
        for (int o = 16; o > 0; o >>= 1) s += __shfl_xor_sync(0xffffffffu, s, o);
        if (lane == 0) {
            float mean = s / (float)N_TOK;
            float d = (1.0f / E_EXP) - mean;
            dsq[wid] = d * d;
        }
    }
    __syncthreads();
    if (tid == 0 && out_size > N_TOK * D_DIM) {
        float l = 0.f;
        for (int e = 0; e < E_EXP; e++) l += dsq[e];
        out[N_TOK * D_DIM] = (l / E_EXP) * 1e-4f;
    }
}

// ---------------- scatter ----------------
__global__ void scatter_kernel() {
    const int n = blockIdx.x * blockDim.x + threadIdx.x;
    if (n >= N_TOK) return;
#pragma unroll
    for (int k = 0; k < 2; k++) {
        int e = g_topi[2 * n + k];
        int i = atomicAdd(&g_cnt2[e], 1);
        int p = g_off[e] + i;
        g_tok[p] = n;
        g_w[p] = g_topw[2 * n + k];
        g_slot[2 * n + k] = p;
    }
}

// ---------------- x -> fp16 hi/lo ----------------
__global__ void convert_x_kernel(const float* __restrict__ x) {
    const int i = blockIdx.x * blockDim.x + threadIdx.x;
    if (i >= N_TOK * D_DIM / 4) return;
    float4 v = ((const float4*)x)[i];
    float vv[4] = {v.x, v.y, v.z, v.w};
    unsigned short hs[4], ls[4];
#pragma unroll
    for (int j = 0; j < 4; j++) {
        __half h = __float2half_rn(vv[j]);
        __half l = __float2half_rn(vv[j] - __half2float(h));
        hs[j] = __half_as_ushort(h);
        ls[j] = __half_as_ushort(l);
    }
    ((uint2*)g_xh)[i] = make_uint2((uint32_t)hs[0] | ((uint32_t)hs[1] << 16),
                                   (uint32_t)hs[2] | ((uint32_t)hs[3] << 16));
    ((uint2*)g_xl)[i] = make_uint2((uint32_t)ls[0] | ((uint32_t)ls[1] << 16),
                                   (uint32_t)ls[2] | ((uint32_t)ls[3] << 16));
}

// ---------------- weight transpose to fp16: [E][K][N] fp32 -> [E][N][K] fp16 ----------------
// Tq MUST be the real device address (cudaGetSymbolAddress) — host shadow is silently
// ATS-writable on GB300 and the device array would stay zero (R3/R4 bug).
template <int K, int N>
__global__ void transpose_half_kernel(const float* __restrict__ W,
                                      __half* __restrict__ Tq) {
    __shared__ float t[32][33];
    const int e = blockIdx.z;
    const int n0 = blockIdx.x * 32, k0 = blockIdx.y * 32;
    const int tx = threadIdx.x, ty = threadIdx.y;
    for (int i = ty; i < 32; i += 8)
        t[i][tx] = W[((size_t)e * K + k0 + i) * N + n0 + tx];
    __syncthreads();
    for (int i = ty; i < 32; i += 8) {
        float v = t[tx][i];                       // = in[k0+tx][n0+i]
        Tq[((size_t)e * N + n0 + i) * K + k0 + tx] = __float2half_rn(v);
    }
}

// ---------------- fp16 2-term GEMM via mma.m16n8k16.f16 ----------------
// PASS2=false: h = leaky(gather(x) @ W1q^T + b1) -> g_hh/g_hl (fp16 hi/lo), KDIM=512,  NCOL=1024
// PASS2=true : o = w * leaky(h @ W2q^T + b2)     -> g_out2,                 KDIM=1024, NCOL=512
template <bool PASS2, int KDIM, int NCOL>
__global__ void __launch_bounds__(256, 1)
gemm_f16(const float* __restrict__ bias) {
    extern __shared__ char smem[];
    const int e = blockIdx.z;
    const int cnt = g_cnt[e];
    const int m0 = blockIdx.y * BM;
    if (m0 >= cnt) return;
    const int n0 = blockIdx.x * BN;
    const int off = g_off[e];
    const int tid = threadIdx.x;
    const int wid = tid >> 5, lane = tid & 31;
    const int warp_m = wid >> 2;                 // 0..1 (64 rows)
    const int warp_n = wid & 3;                  // 0..3 (32 cols)
    const int qr = lane >> 2;                    // 0..7
    const int qc = (lane & 3) * 2;               // k/col element pair base

    const uint32_t sbase = smem_u32(smem);
    int* toks = (int*)smem;                      // [0,512)
    const uint32_t TILE0 = 1024;

    if (!PASS2) {
        if (tid < BM) {
            int m = m0 + tid;
            toks[tid] = g_tok[off + (m < cnt ? m : cnt - 1)];
        }
        __syncthreads();
    }

    const char* Ahb = (const char*)(PASS2 ? g_hh : g_xh);
    const char* Alb = (const char*)(PASS2 ? g_hl : g_xl);
    const char* Bqb = (const char*)(PASS2 ? g_w2q : g_w1q);

    // cp.async plan: 4 units of 16B per tile type (128 rows x 8 units)
    size_t aoff[4], boff[4];
    uint32_t dst[4];
#pragma unroll
    for (int t = 0; t < 4; t++) {
        int uu = tid + 256 * t;
        int r = uu >> 3, u = uu & 7;
        dst[t] = (uint32_t)(r * ROWB + u * 16);
        if (!PASS2) {
            aoff[t] = ((size_t)toks[r] * KDIM) * 2 + u * 16;
        } else {
            int m = m0 + r;
            int row = off + (m < cnt ? m : cnt - 1);
            aoff[t] = ((size_t)row * KDIM) * 2 + u * 16;
        }
        boff[t] = ((size_t)(e * NCOL + n0 + r) * KDIM) * 2 + u * 16;
    }

    auto issue_loads = [&](int c, int s) {
        const uint32_t st = sbase + TILE0 + s * STAGE_BYTES;
        const size_t kb = (size_t)c * (KCH * 2);
#pragma unroll
        for (int t = 0; t < 4; t++) {
            cp16(st + dst[t],                  Ahb + aoff[t] + kb);
            cp16(st + TILE_BYTES + dst[t],     Alb + aoff[t] + kb);
            cp16(st + 2 * TILE_BYTES + dst[t], Bqb + boff[t] + kb);
        }
        asm volatile("cp.async.commit_group;" ::: "memory");
    };

    float acc[4][4][4];
#pragma unroll
    for (int f = 0; f < 4; f++)
#pragma unroll
        for (int g = 0; g < 4; g++)
#pragma unroll
            for (int q = 0; q < 4; q++) acc[f][g][q] = 0.f;

    constexpr int C = KDIM / KCH;
    issue_loads(0, 0);
    issue_loads(1, 1);

    uint32_t aRow[4], bRow[4];
#pragma unroll
    for (int f = 0; f < 4; f++) aRow[f] = (uint32_t)((warp_m * 64 + f * 16 + qr) * ROWB);
#pragma unroll
    for (int g = 0; g < 4; g++) bRow[g] = (uint32_t)((warp_n * 32 + g * 8 + qr) * ROWB);

    for (int c = 0; c < C; c++) {
        const int s = c % NSTAGE;
        if (c == C - 1) asm volatile("cp.async.wait_group 0;" ::: "memory");
        else            asm volatile("cp.async.wait_group 1;" ::: "memory");
        __syncthreads();
        if (c + 2 < C) issue_loads(c + 2, (c + 2) % NSTAGE);

        const uint32_t stAh = sbase + TILE0 + s * STAGE_BYTES;
        const uint32_t stAl = stAh + TILE_BYTES;
        const uint32_t stB  = stAh + 2 * TILE_BYTES;

#pragma unroll
        for (int ks = 0; ks < 4; ks++) {
            const uint32_t kb0 = (uint32_t)((ks * 16 + qc) * 2);   // k 0-7 half
            const uint32_t kb1 = kb0 + 16;                          // k 8-15 half
            uint32_t ah[4][4], al[4][4], bq[4][2];
#pragma unroll
            for (int f = 0; f < 4; f++) {
                ah[f][0] = lds32(stAh + aRow[f] + kb0);
                ah[f][1] = lds32(stAh + aRow[f] + 8 * ROWB + kb0);
                ah[f][2] = lds32(stAh + aRow[f] + kb1);
                ah[f][3] = lds32(stAh + aRow[f] + 8 * ROWB + kb1);
                al[f][0] = lds32(stAl + aRow[f] + kb0);
                al[f][1] = lds32(stAl + aRow[f] + 8 * ROWB + kb0);
                al[f][2] = lds32(stAl + aRow[f] + kb1);
                al[f][3] = lds32(stAl + aRow[f] + 8 * ROWB + kb1);
            }
#pragma unroll
            for (int g = 0; g < 4; g++) {
                bq[g][0] = lds32(stB + bRow[g] + kb0);
                bq[g][1] = lds32(stB + bRow[g] + kb1);
            }
#pragma unroll
            for (int f = 0; f < 4; f++)
#pragma unroll
                for (int g = 0; g < 4; g++) {
                    mma_f16(acc[f][g], ah[f], bq[g][0], bq[g][1]);
                    mma_f16(acc[f][g], al[f], bq[g][0], bq[g][1]);
                }
        }
        __syncthreads();
    }

    // ---- epilogue: bias + leaky (+wgt / fp16 hi-lo split), direct stores ----
    const float* bb = bias + e * NCOL + n0;
#pragma unroll
    for (int f = 0; f < 4; f++) {
        const int rbase = warp_m * 64 + f * 16 + qr;
#pragma unroll
        for (int half = 0; half < 2; half++) {
            const int row = rbase + half * 8;
            const int m = m0 + row;
            if (m >= cnt) continue;
            const int grow = off + m;
            float wgt = 0.f;
            if (PASS2) wgt = g_w[grow];
#pragma unroll
            for (int g = 0; g < 4; g++) {
                const int col = warp_n * 32 + g * 8 + qc;
                float v0 = acc[f][g][2 * half + 0] + bb[col];
                float v1 = acc[f][g][2 * half + 1] + bb[col + 1];
                v0 = (v0 > 0.f) ? v0 : 0.01f * v0;
                v1 = (v1 > 0.f) ? v1 : 0.01f * v1;
                const size_t base = (size_t)grow * NCOL + n0 + col;
                if (!PASS2) {
                    __half h0 = __float2half_rn(v0);
                    __half l0 = __float2half_rn(v0 - __half2float(h0));
                    __half h1 = __float2half_rn(v1);
                    __half l1 = __float2half_rn(v1 - __half2float(h1));
                    *(uint32_t*)&g_hh[base] =
                        (uint32_t)__half_as_ushort(h0) | ((uint32_t)__half_as_ushort(h1) << 16);
                    *(uint32_t*)&g_hl[base] =
                        (uint32_t)__half_as_ushort(l0) | ((uint32_t)__half_as_ushort(l1) << 16);
                } else {
                    *(float2*)&g_out2[base] = make_float2(wgt * v0, wgt * v1);
                }
            }
        }
    }
}

// ---------------- combine ----------------
__global__ void combine_kernel(float* __restrict__ out) {
    const int t = blockIdx.x * blockDim.x + threadIdx.x;
    if (t >= N_TOK * (D_DIM / 4)) return;
    const int n = t / (D_DIM / 4);
    const int d = (t % (D_DIM / 4)) * 4;
    const int s0 = g_slot[2 * n], s1 = g_slot[2 * n + 1];
    float4 a = *(const float4*)(g_out2 + (size_t)s0 * D_DIM + d);
    float4 b = *(const float4*)(g_out2 + (size_t)s1 * D_DIM + d);
    float4 r; r.x = a.x + b.x; r.y = a.y + b.y; r.z = a.z + b.z; r.w = a.w + b.w;
    *(float4*)(out + (size_t)n * D_DIM + d) = r;
}

extern "C" void kernel_launch(void* const* d_in, const int* in_sizes, int n_in,
                              void* d_out, int out_size) {
    const float* x  = (const float*)d_in[0];
    const float* Wr = (const float*)d_in[1];
    const float* br = (const float*)d_in[2];
    const float* W1 = (const float*)d_in[3];
    const float* b1 = (const float*)d_in[4];
    const float* W2 = (const float*)d_in[5];
    const float* b2 = (const float*)d_in[6];
    float* out = (float*)d_out;

    cudaFuncSetAttribute(gemm_f16<false, D_DIM, H_DIM>,
                         cudaFuncAttributeMaxDynamicSharedMemorySize, SMEM_DYN);
    cudaFuncSetAttribute(gemm_f16<true, H_DIM, D_DIM>,
                         cudaFuncAttributeMaxDynamicSharedMemorySize, SMEM_DYN);

    // REAL device addresses of __device__ scratch (never pass symbols from host!)
    __half *w1q, *w2q;
    cudaGetSymbolAddress((void**)&w1q, g_w1q);
    cudaGetSymbolAddress((void**)&w2q, g_w2q);

    init_kernel<<<1, 32>>>();
    router_kernel<<<RBLK, 256>>>(x, Wr, br);
    offsets_loss_kernel<<<1, 256>>>(out, out_size);
    scatter_kernel<<<(N_TOK + 255) / 256, 256>>>();
    convert_x_kernel<<<(N_TOK * D_DIM / 4 + 255) / 256, 256>>>(x);
    transpose_half_kernel<D_DIM, H_DIM>
        <<<dim3(H_DIM / 32, D_DIM / 32, E_EXP), dim3(32, 8)>>>(W1, w1q);
    transpose_half_kernel<H_DIM, D_DIM>
        <<<dim3(D_DIM / 32, H_DIM / 32, E_EXP), dim3(32, 8)>>>(W2, w2q);

    gemm_f16<false, D_DIM, H_DIM>
        <<<dim3(H_DIM / BN, N_TOK / BM, E_EXP), 256, SMEM_DYN>>>(b1);
    gemm_f16<true, H_DIM, D_DIM>
        <<<dim3(D_DIM / BN, N_TOK / BM, E_EXP), 256, SMEM_DYN>>>(b2);
    combine_kernel<<<(N_TOK * D_DIM / 4 + 255) / 256, 256>>>(out);
}

// round 8
// speedup vs baseline: 3.9758x; 1.3977x over previous
#include <cuda_runtime.h>
#include <cuda_fp16.h>
#include <cstdint>

// Problem dims: B=8, T=2048 -> N=16384 tokens, D=512, E=8, H=1024, top_k=2
#define N_TOK   16384
#define D_DIM   512
#define E_EXP   8
#define H_DIM   1024
#define NPAIR   (2 * N_TOK)
#define RBLK    (N_TOK / 8)

#define BM 128
#define BN 128
#define KCH 64                       // 64 fp16 = 128B of data per row per chunk
#define ROWB 144                     // smem row stride (128B data + 16B pad)
#define TILE_BYTES (128 * ROWB)      // 18432
#define STAGE_BYTES (2 * TILE_BYTES) // A, B = 36864
#define NSTAGE 3
#define SMEM_DYN (1024 + NSTAGE * STAGE_BYTES)   // 111616 B

// ---------------- scratch (static device globals) ----------------
__device__ __align__(1024) __half g_xq[(size_t)N_TOK * D_DIM];
__device__ __align__(1024) __half g_w1q[(size_t)E_EXP * H_DIM * D_DIM]; // [E][H][D] K-major
__device__ __align__(1024) __half g_w2q[(size_t)E_EXP * D_DIM * H_DIM]; // [E][D][H] K-major
__device__ __align__(1024) __half g_hq[(size_t)NPAIR * H_DIM];
__device__ __align__(1024) float g_out2[(size_t)NPAIR * D_DIM];
__device__ int   g_tok[NPAIR];
__device__ float g_w[NPAIR];
__device__ int   g_slot[NPAIR];
__device__ int   g_topi[NPAIR];
__device__ float g_topw[NPAIR];
__device__ int   g_cnt[E_EXP];
__device__ int   g_cnt2[E_EXP];
__device__ int   g_off[E_EXP];
__device__ float g_psums[RBLK * E_EXP];

// ---------------- PTX helpers (baseline ISA only) ----------------
__device__ __forceinline__ uint32_t smem_u32(const void* p) {
    uint32_t a;
    asm("{ .reg .u64 t; cvta.to.shared.u64 t, %1; cvt.u32.u64 %0, t; }" : "=r"(a) : "l"(p));
    return a;
}
__device__ __forceinline__ void cp16(uint32_t dst, const void* src) {
    asm volatile("cp.async.cg.shared.global [%0], [%1], 16;" :: "r"(dst), "l"(src));
}
__device__ __forceinline__ uint32_t lds32(uint32_t addr) {
    uint32_t v;
    asm volatile("ld.shared.b32 %0, [%1];" : "=r"(v) : "r"(addr));
    return v;
}
__device__ __forceinline__ void mma_f16(float* c, const uint32_t* a, uint32_t b0, uint32_t b1) {
    asm volatile(
        "mma.sync.aligned.m16n8k16.row.col.f32.f16.f16.f32 "
        "{%0,%1,%2,%3}, {%4,%5,%6,%7}, {%8,%9}, {%0,%1,%2,%3};"
        : "+f"(c[0]), "+f"(c[1]), "+f"(c[2]), "+f"(c[3])
        : "r"(a[0]), "r"(a[1]), "r"(a[2]), "r"(a[3]), "r"(b0), "r"(b1));
}

// ---------------- init ----------------
__global__ void init_kernel() {
    int t = threadIdx.x;
    if (t < E_EXP) { g_cnt[t] = 0; g_cnt2[t] = 0; }
}

// ---------------- router ----------------
__global__ void router_kernel(const float* __restrict__ x,
                              const float* __restrict__ Wr,
                              const float* __restrict__ br) {
    __shared__ float ps[8][E_EXP];
    const int wid = threadIdx.x >> 5, lane = threadIdx.x & 31;
    const int n = blockIdx.x * 8 + wid;
    const float* xr = x + (size_t)n * D_DIM;
    float acc[E_EXP];
#pragma unroll
    for (int e = 0; e < E_EXP; e++) acc[e] = 0.f;
    for (int i = lane; i < D_DIM; i += 32) {
        float xv = xr[i];
        const float* w = Wr + i * E_EXP;
#pragma unroll
        for (int e = 0; e < E_EXP; e++) acc[e] += xv * w[e];
    }
#pragma unroll
    for (int e = 0; e < E_EXP; e++)
#pragma unroll
        for (int o = 16; o > 0; o >>= 1)
            acc[e] += __shfl_xor_sync(0xffffffffu, acc[e], o);

    if (lane == 0) {
        float mx = -1e30f;
#pragma unroll
        for (int e = 0; e < E_EXP; e++) { acc[e] += br[e]; mx = fmaxf(mx, acc[e]); }
        float s = 0.f;
#pragma unroll
        for (int e = 0; e < E_EXP; e++) { acc[e] = expf(acc[e] - mx); s += acc[e]; }
        const float inv = 1.f / s;
        float p1 = -1.f, p2 = -1.f; int i1 = 0, i2 = 0;
#pragma unroll
        for (int e = 0; e < E_EXP; e++) {
            float p = acc[e] * inv;
            ps[wid][e] = p;
            if (p > p1)      { p2 = p1; i2 = i1; p1 = p; i1 = e; }
            else if (p > p2) { p2 = p; i2 = e; }
        }
        g_topi[2 * n] = i1;     g_topw[2 * n] = p1;
        g_topi[2 * n + 1] = i2; g_topw[2 * n + 1] = p2;
        atomicAdd(&g_cnt[i1], 1);
        atomicAdd(&g_cnt[i2], 1);
    }
    __syncthreads();
    if (threadIdx.x < E_EXP) {
        float s = 0.f;
#pragma unroll
        for (int w = 0; w < 8; w++) s += ps[w][threadIdx.x];
        g_psums[blockIdx.x * E_EXP + threadIdx.x] = s;
    }
}

// ---------------- offsets + gating loss ----------------
__global__ void offsets_loss_kernel(float* __restrict__ out, int out_size) {
    __shared__ float dsq[E_EXP];
    const int tid = threadIdx.x;
    if (tid == 0) {
        int o = 0;
        for (int e = 0; e < E_EXP; e++) { g_off[e] = o; o += g_cnt[e]; }
    }
    const int wid = tid >> 5, lane = tid & 31;
    if (wid < E_EXP) {
        float s = 0.f;
        for (int b = lane; b < RBLK; b += 32) s += g_psums[b * E_EXP + wid];
#pragma unroll
        for (int o = 16; o > 0; o >>= 1) s += __shfl_xor_sync(0xffffffffu, s, o);
        if (lane == 0) {
            float mean = s / (float)N_TOK;
            float d = (1.0f / E_EXP) - mean;
            dsq[wid] = d * d;
        }
    }
    __syncthreads();
    if (tid == 0 && out_size > N_TOK * D_DIM) {
        float l = 0.f;
        for (int e = 0; e < E_EXP; e++) l += dsq[e];
        out[N_TOK * D_DIM] = (l / E_EXP) * 1e-4f;
    }
}

// ---------------- scatter ----------------
__global__ void scatter_kernel() {
    const int n = blockIdx.x * blockDim.x + threadIdx.x;
    if (n >= N_TOK) return;
#pragma unroll
    for (int k = 0; k < 2; k++) {
        int e = g_topi[2 * n + k];
        int i = atomicAdd(&g_cnt2[e], 1);
        int p = g_off[e] + i;
        g_tok[p] = n;
        g_w[p] = g_topw[2 * n + k];
        g_slot[2 * n + k] = p;
    }
}

// ---------------- x -> fp16 ----------------
__global__ void convert_x_kernel(const float* __restrict__ x) {
    const int i = blockIdx.x * blockDim.x + threadIdx.x;
    if (i >= N_TOK * D_DIM / 4) return;
    float4 v = ((const float4*)x)[i];
    unsigned short s0 = __half_as_ushort(__float2half_rn(v.x));
    unsigned short s1 = __half_as_ushort(__float2half_rn(v.y));
    unsigned short s2 = __half_as_ushort(__float2half_rn(v.z));
    unsigned short s3 = __half_as_ushort(__float2half_rn(v.w));
    ((uint2*)g_xq)[i] = make_uint2((uint32_t)s0 | ((uint32_t)s1 << 16),
                                   (uint32_t)s2 | ((uint32_t)s3 << 16));
}

// ---------------- weight transpose to fp16: [E][K][N] fp32 -> [E][N][K] fp16 ----------------
// Tq MUST be the real device address (cudaGetSymbolAddress) — host shadow is silently
// ATS-writable on GB300 and the device array would stay zero (R3/R4 bug).
template <int K, int N>
__global__ void transpose_half_kernel(const float* __restrict__ W,
                                      __half* __restrict__ Tq) {
    __shared__ float t[32][33];
    const int e = blockIdx.z;
    const int n0 = blockIdx.x * 32, k0 = blockIdx.y * 32;
    const int tx = threadIdx.x, ty = threadIdx.y;
    for (int i = ty; i < 32; i += 8)
        t[i][tx] = W[((size_t)e * K + k0 + i) * N + n0 + tx];
    __syncthreads();
    for (int i = ty; i < 32; i += 8) {
        float v = t[tx][i];                       // = in[k0+tx][n0+i]
        Tq[((size_t)e * N + n0 + i) * K + k0 + tx] = __float2half_rn(v);
    }
}

// ---------------- fp16 single-plane GEMM via mma.m16n8k16.f16 ----------------
// PASS2=false: h = leaky(gather(xq) @ W1q^T + b1) -> g_hq (fp16), KDIM=512,  NCOL=1024
// PASS2=true : o = w * leaky(hq @ W2q^T + b2)     -> g_out2,      KDIM=1024, NCOL=512
template <bool PASS2, int KDIM, int NCOL>
__global__ void __launch_bounds__(256, 1)
gemm_f16(const float* __restrict__ bias) {
    extern __shared__ char smem[];
    const int e = blockIdx.z;
    const int cnt = g_cnt[e];
    const int m0 = blockIdx.y * BM;
    if (m0 >= cnt) return;
    const int n0 = blockIdx.x * BN;
    const int off = g_off[e];
    const int tid = threadIdx.x;
    const int wid = tid >> 5, lane = tid & 31;
    const int warp_m = wid >> 2;                 // 0..1 (64 rows)
    const int warp_n = wid & 3;                  // 0..3 (32 cols)
    const int qr = lane >> 2;                    // 0..7
    const int qc = (lane & 3) * 2;               // k/col element pair base

    const uint32_t sbase = smem_u32(smem);
    int* toks = (int*)smem;                      // [0,512)
    const uint32_t TILE0 = 1024;

    if (!PASS2) {
        if (tid < BM) {
            int m = m0 + tid;
            toks[tid] = g_tok[off + (m < cnt ? m : cnt - 1)];
        }
        __syncthreads();
    }

    const char* Aqb = (const char*)(PASS2 ? g_hq : g_xq);
    const char* Bqb = (const char*)(PASS2 ? g_w2q : g_w1q);

    // cp.async plan: 4 units of 16B per tile type (128 rows x 8 units)
    size_t aoff[4], boff[4];
    uint32_t dst[4];
#pragma unroll
    for (int t = 0; t < 4; t++) {
        int uu = tid + 256 * t;
        int r = uu >> 3, u = uu & 7;
        dst[t] = (uint32_t)(r * ROWB + u * 16);
        if (!PASS2) {
            aoff[t] = ((size_t)toks[r] * KDIM) * 2 + u * 16;
        } else {
            int m = m0 + r;
            int row = off + (m < cnt ? m : cnt - 1);
            aoff[t] = ((size_t)row * KDIM) * 2 + u * 16;
        }
        boff[t] = ((size_t)(e * NCOL + n0 + r) * KDIM) * 2 + u * 16;
    }

    auto issue_loads = [&](int c, int s) {
        const uint32_t st = sbase + TILE0 + s * STAGE_BYTES;
        const size_t kb = (size_t)c * (KCH * 2);
#pragma unroll
        for (int t = 0; t < 4; t++) {
            cp16(st + dst[t],              Aqb + aoff[t] + kb);
            cp16(st + TILE_BYTES + dst[t], Bqb + boff[t] + kb);
        }
        asm volatile("cp.async.commit_group;" ::: "memory");
    };

    float acc[4][4][4];
#pragma unroll
    for (int f = 0; f < 4; f++)
#pragma unroll
        for (int g = 0; g < 4; g++)
#pragma unroll
            for (int q = 0; q < 4; q++) acc[f][g][q] = 0.f;

    constexpr int C = KDIM / KCH;
    issue_loads(0, 0);
    issue_loads(1, 1);

    uint32_t aRow[4], bRow[4];
#pragma unroll
    for (int f = 0; f < 4; f++) aRow[f] = (uint32_t)((warp_m * 64 + f * 16 + qr) * ROWB);
#pragma unroll
    for (int g = 0; g < 4; g++) bRow[g] = (uint32_t)((warp_n * 32 + g * 8 + qr) * ROWB);

    for (int c = 0; c < C; c++) {
        const int s = c % NSTAGE;
        if (c == C - 1) asm volatile("cp.async.wait_group 0;" ::: "memory");
        else            asm volatile("cp.async.wait_group 1;" ::: "memory");
        __syncthreads();
        if (c + 2 < C) issue_loads(c + 2, (c + 2) % NSTAGE);

        const uint32_t stA = sbase + TILE0 + s * STAGE_BYTES;
        const uint32_t stB = stA + TILE_BYTES;

#pragma unroll
        for (int ks = 0; ks < 4; ks++) {
            const uint32_t kb0 = (uint32_t)((ks * 16 + qc) * 2);   // k 0-7 half
            const uint32_t kb1 = kb0 + 16;                          // k 8-15 half
            uint32_t aq[4][4], bq[4][2];
#pragma unroll
            for (int f = 0; f < 4; f++) {
                aq[f][0] = lds32(stA + aRow[f] + kb0);
                aq[f][1] = lds32(stA + aRow[f] + 8 * ROWB + kb0);
                aq[f][2] = lds32(stA + aRow[f] + kb1);
                aq[f][3] = lds32(stA + aRow[f] + 8 * ROWB + kb1);
            }
#pragma unroll
            for (int g = 0; g < 4; g++) {
                bq[g][0] = lds32(stB + bRow[g] + kb0);
                bq[g][1] = lds32(stB + bRow[g] + kb1);
            }
#pragma unroll
            for (int f = 0; f < 4; f++)
#pragma unroll
                for (int g = 0; g < 4; g++)
                    mma_f16(acc[f][g], aq[f], bq[g][0], bq[g][1]);
        }
        __syncthreads();
    }

    // ---- epilogue: bias + leaky (+wgt / fp16 round), direct stores ----
    const float* bb = bias + e * NCOL + n0;
#pragma unroll
    for (int f = 0; f < 4; f++) {
        const int rbase = warp_m * 64 + f * 16 + qr;
#pragma unroll
        for (int half = 0; half < 2; half++) {
            const int row = rbase + half * 8;
            const int m = m0 + row;
            if (m >= cnt) continue;
            const int grow = off + m;
            float wgt = 0.f;
            if (PASS2) wgt = g_w[grow];
#pragma unroll
            for (int g = 0; g < 4; g++) {
                const int col = warp_n * 32 + g * 8 + qc;
                float v0 = acc[f][g][2 * half + 0] + bb[col];
                float v1 = acc[f][g][2 * half + 1] + bb[col + 1];
                v0 = (v0 > 0.f) ? v0 : 0.01f * v0;
                v1 = (v1 > 0.f) ? v1 : 0.01f * v1;
                const size_t base = (size_t)grow * NCOL + n0 + col;
                if (!PASS2) {
                    *(uint32_t*)&g_hq[base] =
                        (uint32_t)__half_as_ushort(__float2half_rn(v0)) |
                        ((uint32_t)__half_as_ushort(__float2half_rn(v1)) << 16);
                } else {
                    *(float2*)&g_out2[base] = make_float2(wgt * v0, wgt * v1);
                }
            }
        }
    }
}

// ---------------- combine ----------------
__global__ void combine_kernel(float* __restrict__ out) {
    const int t = blockIdx.x * blockDim.x + threadIdx.x;
    if (t >= N_TOK * (D_DIM / 4)) return;
    const int n = t / (D_DIM / 4);
    const int d = (t % (D_DIM / 4)) * 4;
    const int s0 = g_slot[2 * n], s1 = g_slot[2 * n + 1];
    float4 a = *(const float4*)(g_out2 + (size_t)s0 * D_DIM + d);
    float4 b = *(const float4*)(g_out2 + (size_t)s1 * D_DIM + d);
    float4 r; r.x = a.x + b.x; r.y = a.y + b.y; r.z = a.z + b.z; r.w = a.w + b.w;
    *(float4*)(out + (size_t)n * D_DIM + d) = r;
}

extern "C" void kernel_launch(void* const* d_in, const int* in_sizes, int n_in,
                              void* d_out, int out_size) {
    const float* x  = (const float*)d_in[0];
    const float* Wr = (const float*)d_in[1];
    const float* br = (const float*)d_in[2];
    const float* W1 = (const float*)d_in[3];
    const float* b1 = (const float*)d_in[4];
    const float* W2 = (const float*)d_in[5];
    const float* b2 = (const float*)d_in[6];
    float* out = (float*)d_out;

    cudaFuncSetAttribute(gemm_f16<false, D_DIM, H_DIM>,
                         cudaFuncAttributeMaxDynamicSharedMemorySize, SMEM_DYN);
    cudaFuncSetAttribute(gemm_f16<true, H_DIM, D_DIM>,
                         cudaFuncAttributeMaxDynamicSharedMemorySize, SMEM_DYN);

    // REAL device addresses of __device__ scratch (never pass symbols from host!)
    __half *w1q, *w2q;
    cudaGetSymbolAddress((void**)&w1q, g_w1q);
    cudaGetSymbolAddress((void**)&w2q, g_w2q);

    init_kernel<<<1, 32>>>();
    router_kernel<<<RBLK, 256>>>(x, Wr, br);
    offsets_loss_kernel<<<1, 256>>>(out, out_size);
    scatter_kernel<<<(N_TOK + 255) / 256, 256>>>();
    convert_x_kernel<<<(N_TOK * D_DIM / 4 + 255) / 256, 256>>>(x);
    transpose_half_kernel<D_DIM, H_DIM>
        <<<dim3(H_DIM / 32, D_DIM / 32, E_EXP), dim3(32, 8)>>>(W1, w1q);
    transpose_half_kernel<H_DIM, D_DIM>
        <<<dim3(D_DIM / 32, H_DIM / 32, E_EXP), dim3(32, 8)>>>(W2, w2q);

    gemm_f16<false, D_DIM, H_DIM>
        <<<dim3(H_DIM / BN, N_TOK / BM, E_EXP), 256, SMEM_DYN>>>(b1);
    gemm_f16<true, H_DIM, D_DIM>
        <<<dim3(D_DIM / BN, N_TOK / BM, E_EXP), 256, SMEM_DYN>>>(b2);
    combine_kernel<<<(N_TOK * D_DIM / 4 + 255) / 256, 256>>>(out);
}

// round 9
// speedup vs baseline: 5.0901x; 1.2803x over previous
#include <cuda_runtime.h>
#include <cuda_fp16.h>
#include <cstdint>

// Problem dims: B=8, T=2048 -> N=16384 tokens, D=512, E=8, H=1024, top_k=2
#define N_TOK   16384
#define D_DIM   512
#define E_EXP   8
#define H_DIM   1024
#define NPAIR   (2 * N_TOK)
#define RBLK    (N_TOK / 8)

#define BM 128
#define BN 128
#define KCH 64                       // 64 fp16 = 128B of data per row per chunk
#define ROWB 144                     // smem row stride (128B data + 16B pad)
#define TILE_BYTES (128 * ROWB)      // 18432
#define STAGE_BYTES (2 * TILE_BYTES) // A, B = 36864
#define NSTAGE 3
#define SMEM_DYN (1024 + NSTAGE * STAGE_BYTES)   // 111616 B (2 CTAs/SM: 223232 <= 227KB)

// ---------------- scratch (static device globals) ----------------
__device__ __align__(1024) __half g_xq[(size_t)N_TOK * D_DIM];
__device__ __align__(1024) __half g_w1q[(size_t)E_EXP * H_DIM * D_DIM]; // [E][H][D] K-major
__device__ __align__(1024) __half g_w2q[(size_t)E_EXP * D_DIM * H_DIM]; // [E][D][H] K-major
__device__ __align__(1024) __half g_hq[(size_t)NPAIR * H_DIM];
__device__ __align__(1024) float g_out2[(size_t)NPAIR * D_DIM];
__device__ int   g_tok[NPAIR];
__device__ float g_w[NPAIR];
__device__ int   g_slot[NPAIR];
__device__ int   g_topi[NPAIR];
__device__ float g_topw[NPAIR];
__device__ int   g_cnt[E_EXP];
__device__ int   g_cnt2[E_EXP];
__device__ int   g_off[E_EXP];
__device__ float g_psums[RBLK * E_EXP];

// ---------------- PTX helpers (baseline ISA only) ----------------
__device__ __forceinline__ uint32_t smem_u32(const void* p) {
    uint32_t a;
    asm("{ .reg .u64 t; cvta.to.shared.u64 t, %1; cvt.u32.u64 %0, t; }" : "=r"(a) : "l"(p));
    return a;
}
__device__ __forceinline__ void cp16(uint32_t dst, const void* src) {
    asm volatile("cp.async.cg.shared.global [%0], [%1], 16;" :: "r"(dst), "l"(src));
}
__device__ __forceinline__ void ldsm4(uint32_t* r, uint32_t addr) {
    asm volatile("ldmatrix.sync.aligned.m8n8.x4.shared.b16 {%0,%1,%2,%3}, [%4];"
                 : "=r"(r[0]), "=r"(r[1]), "=r"(r[2]), "=r"(r[3]) : "r"(addr));
}
__device__ __forceinline__ void mma_f16(float* c, const uint32_t* a, uint32_t b0, uint32_t b1) {
    asm volatile(
        "mma.sync.aligned.m16n8k16.row.col.f32.f16.f16.f32 "
        "{%0,%1,%2,%3}, {%4,%5,%6,%7}, {%8,%9}, {%0,%1,%2,%3};"
        : "+f"(c[0]), "+f"(c[1]), "+f"(c[2]), "+f"(c[3])
        : "r"(a[0]), "r"(a[1]), "r"(a[2]), "r"(a[3]), "r"(b0), "r"(b1));
}

// ---------------- init ----------------
__global__ void init_kernel() {
    int t = threadIdx.x;
    if (t < E_EXP) { g_cnt[t] = 0; g_cnt2[t] = 0; }
}

// ---------------- router ----------------
__global__ void router_kernel(const float* __restrict__ x,
                              const float* __restrict__ Wr,
                              const float* __restrict__ br) {
    __shared__ float ps[8][E_EXP];
    const int wid = threadIdx.x >> 5, lane = threadIdx.x & 31;
    const int n = blockIdx.x * 8 + wid;
    const float* xr = x + (size_t)n * D_DIM;
    float acc[E_EXP];
#pragma unroll
    for (int e = 0; e < E_EXP; e++) acc[e] = 0.f;
    for (int i = lane; i < D_DIM; i += 32) {
        float xv = xr[i];
        const float* w = Wr + i * E_EXP;
#pragma unroll
        for (int e = 0; e < E_EXP; e++) acc[e] += xv * w[e];
    }
#pragma unroll
    for (int e = 0; e < E_EXP; e++)
#pragma unroll
        for (int o = 16; o > 0; o >>= 1)
            acc[e] += __shfl_xor_sync(0xffffffffu, acc[e], o);

    if (lane == 0) {
        float mx = -1e30f;
#pragma unroll
        for (int e = 0; e < E_EXP; e++) { acc[e] += br[e]; mx = fmaxf(mx, acc[e]); }
        float s = 0.f;
#pragma unroll
        for (int e = 0; e < E_EXP; e++) { acc[e] = expf(acc[e] - mx); s += acc[e]; }
        const float inv = 1.f / s;
        float p1 = -1.f, p2 = -1.f; int i1 = 0, i2 = 0;
#pragma unroll
        for (int e = 0; e < E_EXP; e++) {
            float p = acc[e] * inv;
            ps[wid][e] = p;
            if (p > p1)      { p2 = p1; i2 = i1; p1 = p; i1 = e; }
            else if (p > p2) { p2 = p; i2 = e; }
        }
        g_topi[2 * n] = i1;     g_topw[2 * n] = p1;
        g_topi[2 * n + 1] = i2; g_topw[2 * n + 1] = p2;
        atomicAdd(&g_cnt[i1], 1);
        atomicAdd(&g_cnt[i2], 1);
    }
    __syncthreads();
    if (threadIdx.x < E_EXP) {
        float s = 0.f;
#pragma unroll
        for (int w = 0; w < 8; w++) s += ps[w][threadIdx.x];
        g_psums[blockIdx.x * E_EXP + threadIdx.x] = s;
    }
}

// ---------------- offsets + gating loss ----------------
__global__ void offsets_loss_kernel(float* __restrict__ out, int out_size) {
    __shared__ float dsq[E_EXP];
    const int tid = threadIdx.x;
    if (tid == 0) {
        int o = 0;
        for (int e = 0; e < E_EXP; e++) { g_off[e] = o; o += g_cnt[e]; }
    }
    const int wid = tid >> 5, lane = tid & 31;
    if (wid < E_EXP) {
        float s = 0.f;
        for (int b = lane; b < RBLK; b += 32) s += g_psums[b * E_EXP + wid];
#pragma unroll
        for (int o = 16; o > 0; o >>= 1) s += __shfl_xor_sync(0xffffffffu, s, o);
        if (lane == 0) {
            float mean = s / (float)N_TOK;
            float d = (1.0f / E_EXP) - mean;
            dsq[wid] = d * d;
        }
    }
    __syncthreads();
    if (tid == 0 && out_size > N_TOK * D_DIM) {
        float l = 0.f;
        for (int e = 0; e < E_EXP; e++) l += dsq[e];
        out[N_TOK * D_DIM] = (l / E_EXP) * 1e-4f;
    }
}

// ---------------- scatter ----------------
__global__ void scatter_kernel() {
    const int n = blockIdx.x * blockDim.x + threadIdx.x;
    if (n >= N_TOK) return;
#pragma unroll
    for (int k = 0; k < 2; k++) {
        int e = g_topi[2 * n + k];
        int i = atomicAdd(&g_cnt2[e], 1);
        int p = g_off[e] + i;
        g_tok[p] = n;
        g_w[p] = g_topw[2 * n + k];
        g_slot[2 * n + k] = p;
    }
}

// ---------------- x -> fp16 ----------------
__global__ void convert_x_kernel(const float* __restrict__ x) {
    const int i = blockIdx.x * blockDim.x + threadIdx.x;
    if (i >= N_TOK * D_DIM / 4) return;
    float4 v = ((const float4*)x)[i];
    unsigned short s0 = __half_as_ushort(__float2half_rn(v.x));
    unsigned short s1 = __half_as_ushort(__float2half_rn(v.y));
    unsigned short s2 = __half_as_ushort(__float2half_rn(v.z));
    unsigned short s3 = __half_as_ushort(__float2half_rn(v.w));
    ((uint2*)g_xq)[i] = make_uint2((uint32_t)s0 | ((uint32_t)s1 << 16),
                                   (uint32_t)s2 | ((uint32_t)s3 << 16));
}

// ---------------- weight transpose to fp16: [E][K][N] fp32 -> [E][N][K] fp16 ----------------
// Tq MUST be the real device address (cudaGetSymbolAddress) — host shadow is silently
// ATS-writable on GB300 and the device array would stay zero (R3/R4 bug).
template <int K, int N>
__global__ void transpose_half_kernel(const float* __restrict__ W,
                                      __half* __restrict__ Tq) {
    __shared__ float t[32][33];
    const int e = blockIdx.z;
    const int n0 = blockIdx.x * 32, k0 = blockIdx.y * 32;
    const int tx = threadIdx.x, ty = threadIdx.y;
    for (int i = ty; i < 32; i += 8)
        t[i][tx] = W[((size_t)e * K + k0 + i) * N + n0 + tx];
    __syncthreads();
    for (int i = ty; i < 32; i += 8) {
        float v = t[tx][i];                       // = in[k0+tx][n0+i]
        Tq[((size_t)e * N + n0 + i) * K + k0 + tx] = __float2half_rn(v);
    }
}

// ---------------- fp16 single-plane GEMM via mma.m16n8k16.f16 + ldmatrix ----------------
// PASS2=false: h = leaky(gather(xq) @ W1q^T + b1) -> g_hq (fp16), KDIM=512,  NCOL=1024
// PASS2=true : o = w * leaky(hq @ W2q^T + b2)     -> g_out2,      KDIM=1024, NCOL=512
template <bool PASS2, int KDIM, int NCOL>
__global__ void __launch_bounds__(256, 2)
gemm_f16(const float* __restrict__ bias) {
    extern __shared__ char smem[];
    const int e = blockIdx.z;
    const int cnt = g_cnt[e];
    const int m0 = blockIdx.y * BM;
    if (m0 >= cnt) return;
    const int n0 = blockIdx.x * BN;
    const int off = g_off[e];
    const int tid = threadIdx.x;
    const int wid = tid >> 5, lane = tid & 31;
    const int warp_m = wid >> 2;                 // 0..1 (64 rows)
    const int warp_n = wid & 3;                  // 0..3 (32 cols)
    const int qr = lane >> 2;                    // 0..7
    const int qc = (lane & 3) * 2;               // k/col element pair base

    const uint32_t sbase = smem_u32(smem);
    int* toks = (int*)smem;                      // [0,512)
    const uint32_t TILE0 = 1024;

    if (!PASS2) {
        if (tid < BM) {
            int m = m0 + tid;
            toks[tid] = g_tok[off + (m < cnt ? m : cnt - 1)];
        }
        __syncthreads();
    }

    const char* Aqb = (const char*)(PASS2 ? g_hq : g_xq);
    const char* Bqb = (const char*)(PASS2 ? g_w2q : g_w1q);

    // cp.async plan: 4 units of 16B per tile type (128 rows x 8 units)
    size_t aoff[4], boff[4];
    uint32_t dst[4];
#pragma unroll
    for (int t = 0; t < 4; t++) {
        int uu = tid + 256 * t;
        int r = uu >> 3, u = uu & 7;
        dst[t] = (uint32_t)(r * ROWB + u * 16);
        if (!PASS2) {
            aoff[t] = ((size_t)toks[r] * KDIM) * 2 + u * 16;
        } else {
            int m = m0 + r;
            int row = off + (m < cnt ? m : cnt - 1);
            aoff[t] = ((size_t)row * KDIM) * 2 + u * 16;
        }
        boff[t] = ((size_t)(e * NCOL + n0 + r) * KDIM) * 2 + u * 16;
    }

    auto issue_loads = [&](int c, int s) {
        const uint32_t st = sbase + TILE0 + s * STAGE_BYTES;
        const size_t kb = (size_t)c * (KCH * 2);
#pragma unroll
        for (int t = 0; t < 4; t++) {
            cp16(st + dst[t],              Aqb + aoff[t] + kb);
            cp16(st + TILE_BYTES + dst[t], Bqb + boff[t] + kb);
        }
        asm volatile("cp.async.commit_group;" ::: "memory");
    };

    float acc[4][4][4];
#pragma unroll
    for (int f = 0; f < 4; f++)
#pragma unroll
        for (int g = 0; g < 4; g++)
#pragma unroll
            for (int q = 0; q < 4; q++) acc[f][g][q] = 0.f;

    constexpr int C = KDIM / KCH;
    issue_loads(0, 0);
    issue_loads(1, 1);

    // ldmatrix per-thread base offsets (within a tile; add stage base + ks*32)
    // A x4 (frag f): lanes 0-15 -> rows (f*16 + lane&15) @ khalf0, lanes 16-31 -> same rows @ khalf1
    uint32_t aBase[4];
#pragma unroll
    for (int f = 0; f < 4; f++)
        aBase[f] = (uint32_t)((warp_m * 64 + f * 16 + (lane & 15)) * ROWB + (lane >> 4) * 16);
    // B x4 (pair p covers n = warp_n*32 + p*16 .. +15):
    // lanes 0-7: n0-7@k0 | 8-15: n0-7@k8 | 16-23: n8-15@k0 | 24-31: n8-15@k8
    uint32_t bBase[2];
#pragma unroll
    for (int p = 0; p < 2; p++)
        bBase[p] = (uint32_t)((warp_n * 32 + p * 16 + ((lane >> 4) & 1) * 8 + (lane & 7)) * ROWB
                              + ((lane >> 3) & 1) * 16);

    for (int c = 0; c < C; c++) {
        const int s = c % NSTAGE;
        if (c == C - 1) asm volatile("cp.async.wait_group 0;" ::: "memory");
        else            asm volatile("cp.async.wait_group 1;" ::: "memory");
        __syncthreads();
        if (c + 2 < C) issue_loads(c + 2, (c + 2) % NSTAGE);

        const uint32_t stA = sbase + TILE0 + s * STAGE_BYTES;
        const uint32_t stB = stA + TILE_BYTES;

#pragma unroll
        for (int ks = 0; ks < 4; ks++) {
            const uint32_t ko = (uint32_t)(ks * 32);
            uint32_t aq[4][4], bq[2][4];
#pragma unroll
            for (int f = 0; f < 4; f++) ldsm4(aq[f], stA + aBase[f] + ko);
#pragma unroll
            for (int p = 0; p < 2; p++) ldsm4(bq[p], stB + bBase[p] + ko);
#pragma unroll
            for (int f = 0; f < 4; f++)
#pragma unroll
                for (int p = 0; p < 2; p++) {
                    mma_f16(acc[f][2 * p],     aq[f], bq[p][0], bq[p][1]);  // n group p*16+0-7
                    mma_f16(acc[f][2 * p + 1], aq[f], bq[p][2], bq[p][3]);  // n group p*16+8-15
                }
        }
        __syncthreads();
    }

    // ---- epilogue: bias + leaky (+wgt / fp16 round), direct stores ----
    const float* bb = bias + e * NCOL + n0;
#pragma unroll
    for (int f = 0; f < 4; f++) {
        const int rbase = warp_m * 64 + f * 16 + qr;
#pragma unroll
        for (int half = 0; half < 2; half++) {
            const int row = rbase + half * 8;
            const int m = m0 + row;
            if (m >= cnt) continue;
            const int grow = off + m;
            float wgt = 0.f;
            if (PASS2) wgt = g_w[grow];
#pragma unroll
            for (int g = 0; g < 4; g++) {
                const int col = warp_n * 32 + g * 8 + qc;
                float v0 = acc[f][g][2 * half + 0] + bb[col];
                float v1 = acc[f][g][2 * half + 1] + bb[col + 1];
                v0 = (v0 > 0.f) ? v0 : 0.01f * v0;
                v1 = (v1 > 0.f) ? v1 : 0.01f * v1;
                const size_t base = (size_t)grow * NCOL + n0 + col;
                if (!PASS2) {
                    *(uint32_t*)&g_hq[base] =
                        (uint32_t)__half_as_ushort(__float2half_rn(v0)) |
                        ((uint32_t)__half_as_ushort(__float2half_rn(v1)) << 16);
                } else {
                    *(float2*)&g_out2[base] = make_float2(wgt * v0, wgt * v1);
                }
            }
        }
    }
}

// ---------------- combine ----------------
__global__ void combine_kernel(float* __restrict__ out) {
    const int t = blockIdx.x * blockDim.x + threadIdx.x;
    if (t >= N_TOK * (D_DIM / 4)) return;
    const int n = t / (D_DIM / 4);
    const int d = (t % (D_DIM / 4)) * 4;
    const int s0 = g_slot[2 * n], s1 = g_slot[2 * n + 1];
    float4 a = *(const float4*)(g_out2 + (size_t)s0 * D_DIM + d);
    float4 b = *(const float4*)(g_out2 + (size_t)s1 * D_DIM + d);
    float4 r; r.x = a.x + b.x; r.y = a.y + b.y; r.z = a.z + b.z; r.w = a.w + b.w;
    *(float4*)(out + (size_t)n * D_DIM + d) = r;
}

extern "C" void kernel_launch(void* const* d_in, const int* in_sizes, int n_in,
                              void* d_out, int out_size) {
    const float* x  = (const float*)d_in[0];
    const float* Wr = (const float*)d_in[1];
    const float* br = (const float*)d_in[2];
    const float* W1 = (const float*)d_in[3];
    const float* b1 = (const float*)d_in[4];
    const float* W2 = (const float*)d_in[5];
    const float* b2 = (const float*)d_in[6];
    float* out = (float*)d_out;

    cudaFuncSetAttribute(gemm_f16<false, D_DIM, H_DIM>,
                         cudaFuncAttributeMaxDynamicSharedMemorySize, SMEM_DYN);
    cudaFuncSetAttribute(gemm_f16<true, H_DIM, D_DIM>,
                         cudaFuncAttributeMaxDynamicSharedMemorySize, SMEM_DYN);

    // REAL device addresses of __device__ scratch (never pass symbols from host!)
    __half *w1q, *w2q;
    cudaGetSymbolAddress((void**)&w1q, g_w1q);
    cudaGetSymbolAddress((void**)&w2q, g_w2q);

    init_kernel<<<1, 32>>>();
    router_kernel<<<RBLK, 256>>>(x, Wr, br);
    offsets_loss_kernel<<<1, 256>>>(out, out_size);
    scatter_kernel<<<(N_TOK + 255) / 256, 256>>>();
    convert_x_kernel<<<(N_TOK * D_DIM / 4 + 255) / 256, 256>>>(x);
    transpose_half_kernel<D_DIM, H_DIM>
        <<<dim3(H_DIM / 32, D_DIM / 32, E_EXP), dim3(32, 8)>>>(W1, w1q);
    transpose_half_kernel<H_DIM, D_DIM>
        <<<dim3(D_DIM / 32, H_DIM / 32, E_EXP), dim3(32, 8)>>>(W2, w2q);

    gemm_f16<false, D_DIM, H_DIM>
        <<<dim3(H_DIM / BN, N_TOK / BM, E_EXP), 256, SMEM_DYN>>>(b1);
    gemm_f16<true, H_DIM, D_DIM>
        <<<dim3(D_DIM / BN, N_TOK / BM, E_EXP), 256, SMEM_DYN>>>(b2);
    combine_kernel<<<(N_TOK * D_DIM / 4 + 255) / 256, 256>>>(out);
}